// round 4
// baseline (speedup 1.0000x reference)
#include <cuda_runtime.h>
#include <cuda_fp16.h>
#include <math.h>

#define N_ATOMS 100000
#define M_NBR   12
#define F_DIM   64
#define C_DIM   128              // 2F
#define KW      192              // 2F + NBR
#define P_ROWS  (N_ATOMS * M_NBR)  // 1200000
#define BN_EPS  1e-5f

typedef unsigned long long u64;

// ---------------- scratch (device globals: allocation-free) ----------------
__device__ __align__(256) float  g_S [N_ATOMS * C_DIM];             // W_self·a + b
__device__ __align__(256) float  g_P [N_ATOMS * C_DIM];             // W_nbr·a
__device__ __align__(256) __half g_Zh[(size_t)P_ROWS * C_DIM];      // gated pre-BN (307MB fp16)
__device__ __align__(256) float  g_NS[N_ATOMS * F_DIM];             // nbr_sumed pre-BN2
__device__ float g_stats1[2 * C_DIM];   // [sum(128) | sumsq(128)]
__device__ float g_stats2[2 * F_DIM];   // [sum(64)  | sumsq(64)]
__device__ float g_aff1 [2 * C_DIM];    // [scale | shift]
__device__ float g_aff2 [2 * F_DIM];

// ---------------- packed f32x2 helpers (Blackwell FFMA2 path) -------------
__device__ __forceinline__ u64 pack2(float lo, float hi) {
    u64 r;
    asm("mov.b64 %0, {%1, %2};" : "=l"(r) : "r"(__float_as_uint(lo)), "r"(__float_as_uint(hi)));
    return r;
}
__device__ __forceinline__ u64 dup2(float a) {
    u64 r;
    unsigned int u = __float_as_uint(a);
    asm("mov.b64 %0, {%1, %1};" : "=l"(r) : "r"(u));
    return r;
}
__device__ __forceinline__ void unpack2(u64 v, float& lo, float& hi) {
    unsigned int a, b;
    asm("mov.b64 {%0, %1}, %2;" : "=r"(a), "=r"(b) : "l"(v));
    lo = __uint_as_float(a); hi = __uint_as_float(b);
}
__device__ __forceinline__ u64 ffma2(u64 a, u64 b, u64 c) {
    u64 d;
    asm("fma.rn.f32x2 %0, %1, %2, %3;" : "=l"(d) : "l"(a), "l"(b), "l"(c));
    return d;
}
__device__ __forceinline__ u64 add2(u64 a, u64 b) {
    u64 d;
    asm("add.rn.f32x2 %0, %1, %2;" : "=l"(d) : "l"(a), "l"(b));
    return d;
}

__device__ __forceinline__ float softplus_fast(float x) {
    return fmaxf(x, 0.f) + __logf(1.f + __expf(-fabsf(x)));
}

// ---------------- K0: zero the stat accumulators ----------------
__global__ void k0_zero() {
    int t = threadIdx.x;
    if (t < 2 * C_DIM) g_stats1[t] = 0.f;
    if (t < 2 * F_DIM) g_stats2[t] = 0.f;
}

// ---------------- Knop: padding so ncu -s 5 lands on k2 ----------------
__global__ void knop() {}

// ---------------- K1: S[n,c] = b[c] + W_self·a[n] ; P[n,c] = W_nbr·a[n] ----
__global__ __launch_bounds__(128, 4) void k1_selfnbr(
        const float* __restrict__ atom, const float* __restrict__ W,
        const float* __restrict__ b) {
    __shared__ __align__(16) float sW[64 * 128];
    __shared__ __align__(16) float sA[64 * 36];
    const int tid = threadIdx.x;
    const int n0  = blockIdx.x * 32;

    for (int i = tid; i < 32 * 64; i += 128) {
        int r = i >> 6, k = i & 63;
        sA[k * 36 + r] = atom[(n0 + r) * 64 + k];
    }
    const int rg = tid >> 4, cg = tid & 15;
    const int r0 = rg * 4,  c0 = cg * 8;

    for (int half = 0; half < 2; ++half) {
        __syncthreads();
        for (int i = tid; i < 64 * 128; i += 128) {
            int c = i >> 6, k = i & 63;
            sW[k * 128 + c] = W[c * KW + half * 64 + k];
        }
        __syncthreads();

        u64 acc[4][4];
        #pragma unroll
        for (int r = 0; r < 4; r++)
            #pragma unroll
            for (int cp = 0; cp < 4; cp++)
                acc[r][cp] = (half == 0) ? pack2(b[c0 + 2*cp], b[c0 + 2*cp + 1])
                                         : 0ULL;

        #pragma unroll 8
        for (int k = 0; k < 64; ++k) {
            float4 av = *(const float4*)&sA[k * 36 + r0];
            ulonglong2 w0 = *(const ulonglong2*)&sW[k * 128 + c0];
            ulonglong2 w1 = *(const ulonglong2*)&sW[k * 128 + c0 + 4];
            u64 ad[4] = {dup2(av.x), dup2(av.y), dup2(av.z), dup2(av.w)};
            u64 wp[4] = {w0.x, w0.y, w1.x, w1.y};
            #pragma unroll
            for (int r = 0; r < 4; r++)
                #pragma unroll
                for (int cp = 0; cp < 4; cp++)
                    acc[r][cp] = ffma2(ad[r], wp[cp], acc[r][cp]);
        }

        float* dst = (half == 0) ? g_S : g_P;
        #pragma unroll
        for (int r = 0; r < 4; r++) {
            int n = n0 + r0 + r;
            ulonglong2 q0, q1;
            q0.x = acc[r][0]; q0.y = acc[r][1];
            q1.x = acc[r][2]; q1.y = acc[r][3];
            *(ulonglong2*)&dst[n * C_DIM + c0]     = q0;
            *(ulonglong2*)&dst[n * C_DIM + c0 + 4] = q1;
        }
    }
}

// ---------------- K2: Z = S + P[idx] + W_edge·nbr  (+BN1 stats, fp16 store)
__global__ __launch_bounds__(128, 4) void k2_edge(
        const float* __restrict__ nbr, const int* __restrict__ idx,
        const float* __restrict__ W) {
    __shared__ __align__(16) float sW[64 * 128];
    __shared__ __align__(16) float sE[2][64 * 36];
    __shared__ float sSum[128], sSq[128];
    const int tid = threadIdx.x;
    if (tid < 128) { sSum[tid] = 0.f; sSq[tid] = 0.f; }
    for (int i = tid; i < 64 * 128; i += 128) {
        int c = i >> 6, k = i & 63;
        sW[k * 128 + c] = W[c * KW + 128 + k];
    }
    const int rg = tid >> 4, cg = tid & 15;
    const int r0 = rg * 4,  c0 = cg * 8;
    // load assignment: each thread loads 16 elements (row lr, cols lk0..lk0+... )
    const int lr = tid >> 2;          // 0..31 (row)
    const int lk = (tid & 3) * 16;    // 0,16,32,48

    u64 lsum[4], lsq[4];
    #pragma unroll
    for (int cp = 0; cp < 4; cp++) { lsum[cp] = 0ULL; lsq[cp] = 0ULL; }

    const int ntiles = P_ROWS / 32;  // 37500
    int tile = blockIdx.x;
    int cur = 0;

    // preload first tile
    if (tile < ntiles) {
        #pragma unroll
        for (int q = 0; q < 16; q += 4) {
            float4 v = *(const float4*)&nbr[(size_t)(tile * 32 + lr) * 64 + lk + q];
            sE[0][(lk + q)     * 36 + lr] = v.x;
            sE[0][(lk + q + 1) * 36 + lr] = v.y;
            sE[0][(lk + q + 2) * 36 + lr] = v.z;
            sE[0][(lk + q + 3) * 36 + lr] = v.w;
        }
    }
    __syncthreads();

    for (; tile < ntiles; tile += gridDim.x) {
        const int p0 = tile * 32;
        const int nxt = tile + gridDim.x;

        // prefetch next tile into the other buffer (overlaps with FMA below)
        if (nxt < ntiles) {
            #pragma unroll
            for (int q = 0; q < 16; q += 4) {
                float4 v = *(const float4*)&nbr[(size_t)(nxt * 32 + lr) * 64 + lk + q];
                sE[cur ^ 1][(lk + q)     * 36 + lr] = v.x;
                sE[cur ^ 1][(lk + q + 1) * 36 + lr] = v.y;
                sE[cur ^ 1][(lk + q + 2) * 36 + lr] = v.z;
                sE[cur ^ 1][(lk + q + 3) * 36 + lr] = v.w;
            }
        }

        u64 acc[4][4];
        #pragma unroll
        for (int r = 0; r < 4; r++)
            #pragma unroll
            for (int cp = 0; cp < 4; cp++) acc[r][cp] = 0ULL;

        #pragma unroll 8
        for (int k = 0; k < 64; ++k) {
            float4 av = *(const float4*)&sE[cur][k * 36 + r0];
            ulonglong2 w0 = *(const ulonglong2*)&sW[k * 128 + c0];
            ulonglong2 w1 = *(const ulonglong2*)&sW[k * 128 + c0 + 4];
            u64 ad[4] = {dup2(av.x), dup2(av.y), dup2(av.z), dup2(av.w)};
            u64 wp[4] = {w0.x, w0.y, w1.x, w1.y};
            #pragma unroll
            for (int r = 0; r < 4; r++)
                #pragma unroll
                for (int cp = 0; cp < 4; cp++)
                    acc[r][cp] = ffma2(ad[r], wp[cp], acc[r][cp]);
        }

        #pragma unroll
        for (int r = 0; r < 4; r++) {
            const int p = p0 + r0 + r;
            const int n = p / 12;
            const int j = __ldg(&idx[p]);
            ulonglong2 s0 = *(const ulonglong2*)&g_S[n * C_DIM + c0];
            ulonglong2 s1 = *(const ulonglong2*)&g_S[n * C_DIM + c0 + 4];
            ulonglong2 p0v = *(const ulonglong2*)&g_P[j * C_DIM + c0];
            ulonglong2 p1v = *(const ulonglong2*)&g_P[j * C_DIM + c0 + 4];
            u64 z[4];
            z[0] = add2(acc[r][0], add2(s0.x, p0v.x));
            z[1] = add2(acc[r][1], add2(s0.y, p0v.y));
            z[2] = add2(acc[r][2], add2(s1.x, p1v.x));
            z[3] = add2(acc[r][3], add2(s1.y, p1v.y));
            // BN1 stats from exact fp32
            #pragma unroll
            for (int cp = 0; cp < 4; cp++) {
                lsum[cp] = add2(lsum[cp], z[cp]);
                lsq[cp]  = ffma2(z[cp], z[cp], lsq[cp]);
            }
            // fp16 pack: 8 channels -> 16 bytes
            uint4 st;
            {
                float a0,a1,b0,b1,c0f,c1f,d0,d1;
                unpack2(z[0], a0, a1); unpack2(z[1], b0, b1);
                unpack2(z[2], c0f, c1f); unpack2(z[3], d0, d1);
                __half2 h0 = __floats2half2_rn(a0, a1);
                __half2 h1 = __floats2half2_rn(b0, b1);
                __half2 h2 = __floats2half2_rn(c0f, c1f);
                __half2 h3 = __floats2half2_rn(d0, d1);
                st.x = *(unsigned int*)&h0; st.y = *(unsigned int*)&h1;
                st.z = *(unsigned int*)&h2; st.w = *(unsigned int*)&h3;
            }
            __stcs((uint4*)&g_Zh[(size_t)p * C_DIM + c0], st);
        }
        __syncthreads();
        cur ^= 1;
    }

    #pragma unroll
    for (int cp = 0; cp < 4; cp++) {
        float slo, shi, qlo, qhi;
        unpack2(lsum[cp], slo, shi);
        unpack2(lsq[cp],  qlo, qhi);
        atomicAdd(&sSum[c0 + 2*cp],     slo);
        atomicAdd(&sSum[c0 + 2*cp + 1], shi);
        atomicAdd(&sSq[c0 + 2*cp],      qlo);
        atomicAdd(&sSq[c0 + 2*cp + 1],  qhi);
    }
    __syncthreads();
    if (tid < 128) {
        atomicAdd(&g_stats1[tid],        sSum[tid]);
        atomicAdd(&g_stats1[128 + tid],  sSq[tid]);
    }
}

// ---------------- K3: BN1 affine coefficients ----------------
__global__ void k3_aff1(const float* __restrict__ gamma1,
                        const float* __restrict__ beta1) {
    int c = threadIdx.x;  // 128
    float inv  = 1.f / (float)P_ROWS;
    float mean = g_stats1[c] * inv;
    float var  = g_stats1[128 + c] * inv - mean * mean;
    float sc   = gamma1[c] * rsqrtf(var + BN_EPS);
    g_aff1[c]        = sc;
    g_aff1[128 + c]  = beta1[c] - mean * sc;
}

// ---------------- K4: BN1 apply + gate + sum over M + stats2 ----------------
// 256 threads: lane covers 2 channels (half2), 8 atom-lanes per block stride.
__global__ __launch_bounds__(256) void k4_reduce(const float* __restrict__ bw) {
    __shared__ float sSum[64], sSq[64];
    const int tid = threadIdx.x;
    if (tid < 64) { sSum[tid] = 0.f; sSq[tid] = 0.f; }
    __syncthreads();
    const int f2 = (tid & 31) * 2;   // channel pair 0..62
    const int al = tid >> 5;         // 0..7
    const float sc1a = g_aff1[f2],        sh1a = g_aff1[128 + f2];
    const float sc1b = g_aff1[f2 + 1],    sh1b = g_aff1[128 + f2 + 1];
    const float sc2a = g_aff1[64 + f2],   sh2a = g_aff1[192 + f2];
    const float sc2b = g_aff1[64 + f2+1], sh2b = g_aff1[192 + f2 + 1];
    float lsa = 0.f, lqa = 0.f, lsb = 0.f, lqb = 0.f;

    for (int n = blockIdx.x * 8 + al; n < N_ATOMS; n += gridDim.x * 8) {
        float acca = 0.f, accb = 0.f;
        #pragma unroll
        for (int m = 0; m < 12; m++) {
            size_t base = (size_t)(n * 12 + m) * C_DIM;
            __half2 h1 = *(const __half2*)&g_Zh[base + f2];
            __half2 h2 = *(const __half2*)&g_Zh[base + 64 + f2];
            float2 v1 = __half22float2(h1);
            float2 v2 = __half22float2(h2);
            float z1a = fmaf(v1.x, sc1a, sh1a);
            float z1b = fmaf(v1.y, sc1b, sh1b);
            float z2a = fmaf(v2.x, sc2a, sh2a);
            float z2b = fmaf(v2.y, sc2b, sh2b);
            float w  = __ldg(&bw[n * 12 + m]);
            float w2 = w * w;
            float siga = __fdividef(w2, 1.f + __expf(-z1a));
            float sigb = __fdividef(w2, 1.f + __expf(-z1b));
            acca = fmaf(siga, softplus_fast(z2a), acca);
            accb = fmaf(sigb, softplus_fast(z2b), accb);
        }
        *(float2*)&g_NS[n * 64 + f2] = make_float2(acca, accb);
        lsa += acca; lqa = fmaf(acca, acca, lqa);
        lsb += accb; lqb = fmaf(accb, accb, lqb);
    }
    atomicAdd(&sSum[f2],     lsa);
    atomicAdd(&sSum[f2 + 1], lsb);
    atomicAdd(&sSq[f2],      lqa);
    atomicAdd(&sSq[f2 + 1],  lqb);
    __syncthreads();
    if (tid < 64) {
        atomicAdd(&g_stats2[tid],      sSum[tid]);
        atomicAdd(&g_stats2[64 + tid], sSq[tid]);
    }
}

// ---------------- K5: BN2 affine coefficients ----------------
__global__ void k5_aff2(const float* __restrict__ gamma2,
                        const float* __restrict__ beta2) {
    int f = threadIdx.x;  // 64
    float inv  = 1.f / (float)N_ATOMS;
    float mean = g_stats2[f] * inv;
    float var  = g_stats2[64 + f] * inv - mean * mean;
    float sc   = gamma2[f] * rsqrtf(var + BN_EPS);
    g_aff2[f]       = sc;
    g_aff2[64 + f]  = beta2[f] - mean * sc;
}

// ---------------- K6: out = softplus(atom + BN2(NS)) ----------------
__global__ void k6_out(const float* __restrict__ atom, float* __restrict__ out) {
    int i = blockIdx.x * blockDim.x + threadIdx.x;
    if (i < N_ATOMS * F_DIM) {
        int f = i & 63;
        float x = atom[i] + fmaf(g_NS[i], g_aff2[f], g_aff2[64 + f]);
        out[i] = softplus_fast(x);
    }
}

// ---------------- launch ----------------
extern "C" void kernel_launch(void* const* d_in, const int* in_sizes, int n_in,
                              void* d_out, int out_size) {
    const float* atom   = (const float*)d_in[0];
    const float* nbr    = (const float*)d_in[1];
    const float* bw     = (const float*)d_in[2];
    const int*   idx    = (const int*)  d_in[3];
    const float* W      = (const float*)d_in[4];
    const float* b      = (const float*)d_in[5];
    const float* gamma1 = (const float*)d_in[6];
    const float* beta1  = (const float*)d_in[7];
    const float* gamma2 = (const float*)d_in[8];
    const float* beta2  = (const float*)d_in[9];
    float* out = (float*)d_out;

    k0_zero<<<1, 256>>>();
    k1_selfnbr<<<N_ATOMS / 32, 128>>>(atom, W, b);
    knop<<<1, 32>>>();
    k2_edge<<<592, 128>>>(nbr, idx, W);
    k3_aff1<<<1, 128>>>(gamma1, beta1);
    k4_reduce<<<592, 256>>>(bw);
    k5_aff2<<<1, 64>>>(gamma2, beta2);
    k6_out<<<(N_ATOMS * F_DIM + 255) / 256, 256>>>(atom, out);
}

// round 5
// speedup vs baseline: 1.2236x; 1.2236x over previous
#include <cuda_runtime.h>
#include <cuda_fp16.h>
#include <math.h>

#define N_ATOMS 100000
#define M_NBR   12
#define F_DIM   64
#define C_DIM   128              // 2F
#define KW      192              // 2F + NBR
#define P_ROWS  (N_ATOMS * M_NBR)  // 1200000
#define BN_EPS  1e-5f
#define TR      64               // k2 block tile rows
#define PADR    68               // padded row dim of sE

typedef unsigned long long u64;

// ---------------- scratch (device globals: allocation-free) ----------------
__device__ __align__(256) float  g_S [N_ATOMS * C_DIM];             // W_self·a + b
__device__ __align__(256) float  g_P [N_ATOMS * C_DIM];             // W_nbr·a
__device__ __align__(256) __half g_Zh[(size_t)P_ROWS * C_DIM];      // gated pre-BN (307MB fp16)
__device__ __align__(256) float  g_NS[N_ATOMS * F_DIM];             // nbr_sumed pre-BN2
__device__ float g_stats1[2 * C_DIM];
__device__ float g_stats2[2 * F_DIM];
__device__ float g_aff1 [2 * C_DIM];
__device__ float g_aff2 [2 * F_DIM];

// ---------------- packed f32x2 helpers (Blackwell FFMA2 path) -------------
__device__ __forceinline__ u64 pack2(float lo, float hi) {
    u64 r;
    asm("mov.b64 %0, {%1, %2};" : "=l"(r) : "r"(__float_as_uint(lo)), "r"(__float_as_uint(hi)));
    return r;
}
__device__ __forceinline__ u64 dup2(float a) {
    u64 r;
    unsigned int u = __float_as_uint(a);
    asm("mov.b64 %0, {%1, %1};" : "=l"(r) : "r"(u));
    return r;
}
__device__ __forceinline__ void unpack2(u64 v, float& lo, float& hi) {
    unsigned int a, b;
    asm("mov.b64 {%0, %1}, %2;" : "=r"(a), "=r"(b) : "l"(v));
    lo = __uint_as_float(a); hi = __uint_as_float(b);
}
__device__ __forceinline__ u64 ffma2(u64 a, u64 b, u64 c) {
    u64 d;
    asm("fma.rn.f32x2 %0, %1, %2, %3;" : "=l"(d) : "l"(a), "l"(b), "l"(c));
    return d;
}
__device__ __forceinline__ u64 add2(u64 a, u64 b) {
    u64 d;
    asm("add.rn.f32x2 %0, %1, %2;" : "=l"(d) : "l"(a), "l"(b));
    return d;
}
__device__ __forceinline__ float tanh_fast(float x) {
    float y;
    asm("tanh.approx.f32 %0, %1;" : "=f"(y) : "f"(x));
    return y;
}
__device__ __forceinline__ float sigmoid_fast(float x) {
    return fmaf(0.5f, tanh_fast(0.5f * x), 0.5f);   // 1 MUFU
}
__device__ __forceinline__ float softplus_fast(float x) {
    return fmaxf(x, 0.f) + __logf(1.f + __expf(-fabsf(x)));
}

// ---------------- K0: zero the stat accumulators ----------------
__global__ void k0_zero() {
    int t = threadIdx.x;
    if (t < 2 * C_DIM) g_stats1[t] = 0.f;
    if (t < 2 * F_DIM) g_stats2[t] = 0.f;
}

// ---------------- Knop: padding so ncu -s 5 lands on k2 ----------------
__global__ void knop() {}

// ---------------- K1: S[n,c] = b[c] + W_self·a[n] ; P[n,c] = W_nbr·a[n] ----
__global__ __launch_bounds__(128, 4) void k1_selfnbr(
        const float* __restrict__ atom, const float* __restrict__ W,
        const float* __restrict__ b) {
    __shared__ __align__(16) float sW[64 * 128];
    __shared__ __align__(16) float sA[64 * 36];
    const int tid = threadIdx.x;
    const int n0  = blockIdx.x * 32;

    for (int i = tid; i < 32 * 64; i += 128) {
        int r = i >> 6, k = i & 63;
        sA[k * 36 + r] = atom[(n0 + r) * 64 + k];
    }
    const int rg = tid >> 4, cg = tid & 15;
    const int r0 = rg * 4,  c0 = cg * 8;

    for (int half = 0; half < 2; ++half) {
        __syncthreads();
        for (int i = tid; i < 64 * 128; i += 128) {
            int c = i >> 6, k = i & 63;
            sW[k * 128 + c] = W[c * KW + half * 64 + k];
        }
        __syncthreads();

        u64 acc[4][4];
        #pragma unroll
        for (int r = 0; r < 4; r++)
            #pragma unroll
            for (int cp = 0; cp < 4; cp++)
                acc[r][cp] = (half == 0) ? pack2(b[c0 + 2*cp], b[c0 + 2*cp + 1])
                                         : 0ULL;

        #pragma unroll 8
        for (int k = 0; k < 64; ++k) {
            float4 av = *(const float4*)&sA[k * 36 + r0];
            ulonglong2 w0 = *(const ulonglong2*)&sW[k * 128 + c0];
            ulonglong2 w1 = *(const ulonglong2*)&sW[k * 128 + c0 + 4];
            u64 ad[4] = {dup2(av.x), dup2(av.y), dup2(av.z), dup2(av.w)};
            u64 wp[4] = {w0.x, w0.y, w1.x, w1.y};
            #pragma unroll
            for (int r = 0; r < 4; r++)
                #pragma unroll
                for (int cp = 0; cp < 4; cp++)
                    acc[r][cp] = ffma2(ad[r], wp[cp], acc[r][cp]);
        }

        float* dst = (half == 0) ? g_S : g_P;
        #pragma unroll
        for (int r = 0; r < 4; r++) {
            int n = n0 + r0 + r;
            ulonglong2 q0, q1;
            q0.x = acc[r][0]; q0.y = acc[r][1];
            q1.x = acc[r][2]; q1.y = acc[r][3];
            *(ulonglong2*)&dst[n * C_DIM + c0]     = q0;
            *(ulonglong2*)&dst[n * C_DIM + c0 + 4] = q1;
        }
    }
}

// ---------------- K2: Z = S + P[idx] + W_edge·nbr  (+BN1 stats, fp16 store)
// 64-row block tile, 128 threads, 8x8 thread tile (f32x2 packed).
__global__ __launch_bounds__(128, 3) void k2_edge(
        const float* __restrict__ nbr, const int* __restrict__ idx,
        const float* __restrict__ W) {
    __shared__ __align__(16) float sW[64 * 128];        // 32KB
    __shared__ __align__(16) float sE[2][64 * PADR];    // 34.8KB, [k][row]
    __shared__ float sSum[128], sSq[128];
    const int tid = threadIdx.x;
    if (tid < 128) { sSum[tid] = 0.f; sSq[tid] = 0.f; }
    for (int i = tid; i < 64 * 128; i += 128) {
        int c = i >> 6, k = i & 63;
        sW[k * 128 + c] = W[c * KW + 128 + k];
    }
    const int rg = tid >> 4, cg = tid & 15;   // 8 x 16
    const int r0 = rg * 8,  c0 = cg * 8;
    // loader: thread covers rows {lr, lr+32}, k-slice [lk, lk+16)
    const int lr = tid >> 2;          // 0..31
    const int lk = (tid & 3) * 16;    // 0,16,32,48

    u64 lsum[4], lsq[4];
    #pragma unroll
    for (int cp = 0; cp < 4; cp++) { lsum[cp] = 0ULL; lsq[cp] = 0ULL; }

    const int ntiles = P_ROWS / TR;  // 18750
    int tile = blockIdx.x;
    int cur = 0;

    if (tile < ntiles) {
        #pragma unroll
        for (int rr = 0; rr < TR; rr += 32) {
            #pragma unroll
            for (int q = 0; q < 16; q += 4) {
                float4 v = *(const float4*)&nbr[(size_t)(tile * TR + lr + rr) * 64 + lk + q];
                sE[0][(lk + q)     * PADR + lr + rr] = v.x;
                sE[0][(lk + q + 1) * PADR + lr + rr] = v.y;
                sE[0][(lk + q + 2) * PADR + lr + rr] = v.z;
                sE[0][(lk + q + 3) * PADR + lr + rr] = v.w;
            }
        }
    }
    __syncthreads();

    for (; tile < ntiles; tile += gridDim.x) {
        const int p0 = tile * TR;
        const int nxt = tile + gridDim.x;

        if (nxt < ntiles) {
            #pragma unroll
            for (int rr = 0; rr < TR; rr += 32) {
                #pragma unroll
                for (int q = 0; q < 16; q += 4) {
                    float4 v = *(const float4*)&nbr[(size_t)(nxt * TR + lr + rr) * 64 + lk + q];
                    sE[cur ^ 1][(lk + q)     * PADR + lr + rr] = v.x;
                    sE[cur ^ 1][(lk + q + 1) * PADR + lr + rr] = v.y;
                    sE[cur ^ 1][(lk + q + 2) * PADR + lr + rr] = v.z;
                    sE[cur ^ 1][(lk + q + 3) * PADR + lr + rr] = v.w;
                }
            }
        }

        u64 acc[8][4];
        #pragma unroll
        for (int r = 0; r < 8; r++)
            #pragma unroll
            for (int cp = 0; cp < 4; cp++) acc[r][cp] = 0ULL;

        #pragma unroll 4
        for (int k = 0; k < 64; ++k) {
            float4 a0 = *(const float4*)&sE[cur][k * PADR + r0];
            float4 a1 = *(const float4*)&sE[cur][k * PADR + r0 + 4];
            ulonglong2 w0 = *(const ulonglong2*)&sW[k * 128 + c0];
            ulonglong2 w1 = *(const ulonglong2*)&sW[k * 128 + c0 + 4];
            u64 ad[8] = {dup2(a0.x), dup2(a0.y), dup2(a0.z), dup2(a0.w),
                         dup2(a1.x), dup2(a1.y), dup2(a1.z), dup2(a1.w)};
            u64 wp[4] = {w0.x, w0.y, w1.x, w1.y};
            #pragma unroll
            for (int r = 0; r < 8; r++)
                #pragma unroll
                for (int cp = 0; cp < 4; cp++)
                    acc[r][cp] = ffma2(ad[r], wp[cp], acc[r][cp]);
        }

        #pragma unroll
        for (int r = 0; r < 8; r++) {
            const int p = p0 + r0 + r;
            const int n = p / 12;
            const int j = __ldg(&idx[p]);
            ulonglong2 s0 = *(const ulonglong2*)&g_S[n * C_DIM + c0];
            ulonglong2 s1 = *(const ulonglong2*)&g_S[n * C_DIM + c0 + 4];
            ulonglong2 p0v = *(const ulonglong2*)&g_P[j * C_DIM + c0];
            ulonglong2 p1v = *(const ulonglong2*)&g_P[j * C_DIM + c0 + 4];
            u64 z[4];
            z[0] = add2(acc[r][0], add2(s0.x, p0v.x));
            z[1] = add2(acc[r][1], add2(s0.y, p0v.y));
            z[2] = add2(acc[r][2], add2(s1.x, p1v.x));
            z[3] = add2(acc[r][3], add2(s1.y, p1v.y));
            #pragma unroll
            for (int cp = 0; cp < 4; cp++) {
                lsum[cp] = add2(lsum[cp], z[cp]);
                lsq[cp]  = ffma2(z[cp], z[cp], lsq[cp]);
            }
            uint4 st;
            {
                float a0f,a1f,b0f,b1f,c0f,c1f,d0f,d1f;
                unpack2(z[0], a0f, a1f); unpack2(z[1], b0f, b1f);
                unpack2(z[2], c0f, c1f); unpack2(z[3], d0f, d1f);
                __half2 h0 = __floats2half2_rn(a0f, a1f);
                __half2 h1 = __floats2half2_rn(b0f, b1f);
                __half2 h2 = __floats2half2_rn(c0f, c1f);
                __half2 h3 = __floats2half2_rn(d0f, d1f);
                st.x = *(unsigned int*)&h0; st.y = *(unsigned int*)&h1;
                st.z = *(unsigned int*)&h2; st.w = *(unsigned int*)&h3;
            }
            __stcs((uint4*)&g_Zh[(size_t)p * C_DIM + c0], st);
        }
        __syncthreads();
        cur ^= 1;
    }

    #pragma unroll
    for (int cp = 0; cp < 4; cp++) {
        float slo, shi, qlo, qhi;
        unpack2(lsum[cp], slo, shi);
        unpack2(lsq[cp],  qlo, qhi);
        atomicAdd(&sSum[c0 + 2*cp],     slo);
        atomicAdd(&sSum[c0 + 2*cp + 1], shi);
        atomicAdd(&sSq[c0 + 2*cp],      qlo);
        atomicAdd(&sSq[c0 + 2*cp + 1],  qhi);
    }
    __syncthreads();
    if (tid < 128) {
        atomicAdd(&g_stats1[tid],        sSum[tid]);
        atomicAdd(&g_stats1[128 + tid],  sSq[tid]);
    }
}

// ---------------- K3: BN1 affine coefficients ----------------
__global__ void k3_aff1(const float* __restrict__ gamma1,
                        const float* __restrict__ beta1) {
    int c = threadIdx.x;  // 128
    float inv  = 1.f / (float)P_ROWS;
    float mean = g_stats1[c] * inv;
    float var  = g_stats1[128 + c] * inv - mean * mean;
    float sc   = gamma1[c] * rsqrtf(var + BN_EPS);
    g_aff1[c]        = sc;
    g_aff1[128 + c]  = beta1[c] - mean * sc;
}

// ---------------- K4: BN1 apply + gate + sum over M + stats2 ----------------
__global__ __launch_bounds__(256) void k4_reduce(const float* __restrict__ bw) {
    __shared__ float sSum[64], sSq[64];
    const int tid = threadIdx.x;
    if (tid < 64) { sSum[tid] = 0.f; sSq[tid] = 0.f; }
    __syncthreads();
    const int f2 = (tid & 31) * 2;
    const int al = tid >> 5;         // 0..7
    const float sc1a = g_aff1[f2],        sh1a = g_aff1[128 + f2];
    const float sc1b = g_aff1[f2 + 1],    sh1b = g_aff1[128 + f2 + 1];
    const float sc2a = g_aff1[64 + f2],   sh2a = g_aff1[192 + f2];
    const float sc2b = g_aff1[64 + f2+1], sh2b = g_aff1[192 + f2 + 1];
    float lsa = 0.f, lqa = 0.f, lsb = 0.f, lqb = 0.f;

    for (int n = blockIdx.x * 8 + al; n < N_ATOMS; n += gridDim.x * 8) {
        float acca = 0.f, accb = 0.f;
        #pragma unroll
        for (int m = 0; m < 12; m++) {
            size_t base = (size_t)(n * 12 + m) * C_DIM;
            __half2 h1 = *(const __half2*)&g_Zh[base + f2];
            __half2 h2 = *(const __half2*)&g_Zh[base + 64 + f2];
            float2 v1 = __half22float2(h1);
            float2 v2 = __half22float2(h2);
            float z1a = fmaf(v1.x, sc1a, sh1a);
            float z1b = fmaf(v1.y, sc1b, sh1b);
            float z2a = fmaf(v2.x, sc2a, sh2a);
            float z2b = fmaf(v2.y, sc2b, sh2b);
            float w  = __ldg(&bw[n * 12 + m]);
            float w2 = w * w;
            acca = fmaf(w2 * sigmoid_fast(z1a), softplus_fast(z2a), acca);
            accb = fmaf(w2 * sigmoid_fast(z1b), softplus_fast(z2b), accb);
        }
        *(float2*)&g_NS[n * 64 + f2] = make_float2(acca, accb);
        lsa += acca; lqa = fmaf(acca, acca, lqa);
        lsb += accb; lqb = fmaf(accb, accb, lqb);
    }
    atomicAdd(&sSum[f2],     lsa);
    atomicAdd(&sSum[f2 + 1], lsb);
    atomicAdd(&sSq[f2],      lqa);
    atomicAdd(&sSq[f2 + 1],  lqb);
    __syncthreads();
    if (tid < 64) {
        atomicAdd(&g_stats2[tid],      sSum[tid]);
        atomicAdd(&g_stats2[64 + tid], sSq[tid]);
    }
}

// ---------------- K5: BN2 affine coefficients ----------------
__global__ void k5_aff2(const float* __restrict__ gamma2,
                        const float* __restrict__ beta2) {
    int f = threadIdx.x;  // 64
    float inv  = 1.f / (float)N_ATOMS;
    float mean = g_stats2[f] * inv;
    float var  = g_stats2[64 + f] * inv - mean * mean;
    float sc   = gamma2[f] * rsqrtf(var + BN_EPS);
    g_aff2[f]       = sc;
    g_aff2[64 + f]  = beta2[f] - mean * sc;
}

// ---------------- K6: out = softplus(atom + BN2(NS)) ----------------
__global__ void k6_out(const float* __restrict__ atom, float* __restrict__ out) {
    int i = blockIdx.x * blockDim.x + threadIdx.x;
    if (i < N_ATOMS * F_DIM) {
        int f = i & 63;
        float x = atom[i] + fmaf(g_NS[i], g_aff2[f], g_aff2[64 + f]);
        out[i] = softplus_fast(x);
    }
}

// ---------------- launch ----------------
extern "C" void kernel_launch(void* const* d_in, const int* in_sizes, int n_in,
                              void* d_out, int out_size) {
    const float* atom   = (const float*)d_in[0];
    const float* nbr    = (const float*)d_in[1];
    const float* bw     = (const float*)d_in[2];
    const int*   idx    = (const int*)  d_in[3];
    const float* W      = (const float*)d_in[4];
    const float* b      = (const float*)d_in[5];
    const float* gamma1 = (const float*)d_in[6];
    const float* beta1  = (const float*)d_in[7];
    const float* gamma2 = (const float*)d_in[8];
    const float* beta2  = (const float*)d_in[9];
    float* out = (float*)d_out;

    k0_zero<<<1, 256>>>();
    k1_selfnbr<<<N_ATOMS / 32, 128>>>(atom, W, b);
    knop<<<1, 32>>>();
    k2_edge<<<444, 128>>>(nbr, idx, W);
    k3_aff1<<<1, 128>>>(gamma1, beta1);
    k4_reduce<<<592, 256>>>(bw);
    k5_aff2<<<1, 64>>>(gamma2, beta2);
    k6_out<<<(N_ATOMS * F_DIM + 255) / 256, 256>>>(atom, out);
}